// round 1
// baseline (speedup 1.0000x reference)
#include <cuda_runtime.h>

// DETRsmpl iterative regression head, fused fp32.
// n = 115200 rows, C = 256, theta = 157 (padded 160).
// Restructured: xW1a precomputed once; W2@W3 folded to W23; iter-1 theta GEMM folded to c1.

#define TDIM 157
#define TPAD 160
#define TM 32
#define NTHREADS 256

// ---- device-global scratch (no allocation allowed) ----
__device__ float g_W1bp[TPAD * 256];   // W1 rows 256..412, zero-padded to 160 rows
__device__ float g_W23p[256 * TPAD];   // W2 @ W3, cols zero-padded to 160
__device__ float g_c1[256];            // theta0 @ W1b + b1
__device__ float g_b23[TPAD];          // b2 @ W3 + b3 (padded)
__device__ float g_theta0[TPAD];       // concat(init_contrep, init_shape, init_cam), padded

// ---------------- prep kernels (tiny) ----------------
__global__ void prep_theta0_k(const float* __restrict__ icr,
                              const float* __restrict__ ish,
                              const float* __restrict__ icam) {
    int t = threadIdx.x;  // 160
    float v = 0.f;
    if (t < 144)      v = icr[t];
    else if (t < 154) v = ish[t - 144];
    else if (t < 157) v = icam[t - 154];
    g_theta0[t] = v;
}

__global__ void prep_W1bp_k(const float* __restrict__ W1) {
    int t = blockIdx.x;   // 0..159
    int j = threadIdx.x;  // 0..255
    g_W1bp[t * 256 + j] = (t < 157) ? W1[(256 + t) * 256 + j] : 0.f;
}

__global__ void prep_c1_k(const float* __restrict__ W1, const float* __restrict__ b1) {
    int j = threadIdx.x;  // 0..255
    float s = b1[j];
    for (int t = 0; t < 157; t++)
        s = fmaf(g_theta0[t], W1[(256 + t) * 256 + j], s);
    g_c1[j] = s;
}

__global__ void prep_W23p_k(const float* __restrict__ W2, const float* __restrict__ W3) {
    int k = blockIdx.x;   // 0..255
    int j = threadIdx.x;  // 0..159
    float s = 0.f;
    if (j < 157) {
        for (int m = 0; m < 256; m++)
            s = fmaf(W2[k * 256 + m], W3[m * 157 + j], s);
    }
    g_W23p[k * TPAD + j] = s;
}

__global__ void prep_b23_k(const float* __restrict__ b2, const float* __restrict__ b3,
                           const float* __restrict__ W3) {
    int j = threadIdx.x;  // 0..159
    float s = 0.f;
    if (j < 157) {
        s = b3[j];
        for (int m = 0; m < 256; m++)
            s = fmaf(b2[m], W3[m * 157 + j], s);
    }
    g_b23[j] = s;
}

// ---------------- main fused kernel ----------------
// 16-wide fp32 dot-accumulate: p is 16B-aligned smem (broadcast across warp).
__device__ __forceinline__ float fma16(float acc, const float* __restrict__ p,
                                       const float* __restrict__ w) {
    const float4* q = reinterpret_cast<const float4*>(p);
    float4 a0 = q[0], a1 = q[1], a2 = q[2], a3 = q[3];
    acc = fmaf(a0.x, w[0], acc);  acc = fmaf(a0.y, w[1], acc);
    acc = fmaf(a0.z, w[2], acc);  acc = fmaf(a0.w, w[3], acc);
    acc = fmaf(a1.x, w[4], acc);  acc = fmaf(a1.y, w[5], acc);
    acc = fmaf(a1.z, w[6], acc);  acc = fmaf(a1.w, w[7], acc);
    acc = fmaf(a2.x, w[8], acc);  acc = fmaf(a2.y, w[9], acc);
    acc = fmaf(a2.z, w[10], acc); acc = fmaf(a2.w, w[11], acc);
    acc = fmaf(a3.x, w[12], acc); acc = fmaf(a3.y, w[13], acc);
    acc = fmaf(a3.z, w[14], acc); acc = fmaf(a3.w, w[15], acc);
    return acc;
}

__global__ __launch_bounds__(NTHREADS, 2)
void detr_main(const float* __restrict__ x, const float* __restrict__ W1,
               const float* __restrict__ b1, float* __restrict__ out, int nrows) {
    extern __shared__ float sm[];
    float* Ts = sm;                  // [TM][TPAD] theta tile
    float* Hs = Ts + TM * TPAD;      // [TM][256] relu activations
    float* xs = Hs + TM * 256;       // [TM][16] x k-block staging

    const int tid = threadIdx.x;
    const int row0 = blockIdx.x * TM;
    const float* xbase = x + (size_t)row0 * 256;

    // ---- Phase A: xw[r] = (x_tile @ W1a)[:, tid]  (iteration-invariant) ----
    float xw[TM];
#pragma unroll
    for (int r = 0; r < TM; r++) xw[r] = 0.f;

    for (int kb = 0; kb < 256; kb += 16) {
        __syncthreads();  // protect xs overwrite
        if (tid < TM * 4) {
            int r = tid >> 2, kq = tid & 3;
            *reinterpret_cast<float4*>(&xs[r * 16 + kq * 4]) =
                *reinterpret_cast<const float4*>(xbase + r * 256 + kb + kq * 4);
        }
        float w[16];
#pragma unroll
        for (int kk = 0; kk < 16; kk++)
            w[kk] = __ldg(&W1[(kb + kk) * 256 + tid]);
        __syncthreads();
#pragma unroll 8
        for (int r = 0; r < TM; r++)
            xw[r] = fma16(xw[r], &xs[r * 16], w);
    }

    // ---- 3 refinement iterations ----
    for (int it = 0; it < 3; ++it) {
        float u[TM];
        if (it == 0) {
            // theta is broadcast theta0 -> folded into c1
            float c = g_c1[tid];
#pragma unroll
            for (int r = 0; r < TM; r++) u[r] = xw[r] + c;
        } else {
#pragma unroll
            for (int r = 0; r < TM; r++) u[r] = 0.f;
            // tproj: theta_tile @ W1b  (K = 160 padded)
            for (int kb = 0; kb < TPAD; kb += 16) {
                float w[16];
#pragma unroll
                for (int kk = 0; kk < 16; kk++)
                    w[kk] = g_W1bp[(kb + kk) * 256 + tid];
#pragma unroll 8
                for (int r = 0; r < TM; r++)
                    u[r] = fma16(u[r], &Ts[r * TPAD + kb], w);
            }
            float c = b1[tid];
#pragma unroll
            for (int r = 0; r < TM; r++) u[r] += xw[r] + c;
        }
        // relu -> Hs
#pragma unroll
        for (int r = 0; r < TM; r++)
            Hs[r * 256 + tid] = fmaxf(u[r], 0.f);
        __syncthreads();

        // delta GEMM: h_tile(TMx256) @ W23(256x157->160), thread = output col
        if (tid < TPAD) {
            float acc[TM];
#pragma unroll
            for (int r = 0; r < TM; r++) acc[r] = 0.f;
            for (int kb = 0; kb < 256; kb += 16) {
                float w[16];
#pragma unroll
                for (int kk = 0; kk < 16; kk++)
                    w[kk] = g_W23p[(kb + kk) * TPAD + tid];
#pragma unroll 8
                for (int r = 0; r < TM; r++)
                    acc[r] = fma16(acc[r], &Hs[r * 256 + kb], w);
            }
            float bb = g_b23[tid];
            if (it == 0) {
                float t0 = g_theta0[tid];
#pragma unroll
                for (int r = 0; r < TM; r++)
                    Ts[r * TPAD + tid] = t0 + acc[r] + bb;
            } else {
#pragma unroll
                for (int r = 0; r < TM; r++)
                    Ts[r * TPAD + tid] += acc[r] + bb;
            }
        }
        __syncthreads();
    }

    // ---- epilogue: rot6d -> rotmat, betas, camera ----
    float* out_rot  = out;
    float* out_beta = out + (size_t)nrows * 216;
    float* out_cam  = out + (size_t)nrows * 226;

    for (int idx = tid; idx < TM * 24; idx += NTHREADS) {
        int r = idx / 24, g = idx - 24 * r;
        const float* tp = &Ts[r * TPAD + g * 6];
        // pose reshaped (3,2): column0=a1, column1=a2
        float a1x = tp[0], a2x = tp[1];
        float a1y = tp[2], a2y = tp[3];
        float a1z = tp[4], a2z = tp[5];
        float n1 = sqrtf(a1x * a1x + a1y * a1y + a1z * a1z);
        float i1 = 1.f / fmaxf(n1, 1e-12f);
        float b1x = a1x * i1, b1y = a1y * i1, b1z = a1z * i1;
        float d = b1x * a2x + b1y * a2y + b1z * a2z;
        float c2x = a2x - d * b1x, c2y = a2y - d * b1y, c2z = a2z - d * b1z;
        float n2 = sqrtf(c2x * c2x + c2y * c2y + c2z * c2z);
        float i2 = 1.f / fmaxf(n2, 1e-12f);
        float b2x = c2x * i2, b2y = c2y * i2, b2z = c2z * i2;
        float b3x = b1y * b2z - b1z * b2y;
        float b3y = b1z * b2x - b1x * b2z;
        float b3z = b1x * b2y - b1y * b2x;
        float* o = out_rot + (size_t)(row0 + r) * 216 + g * 9;
        o[0] = b1x; o[1] = b2x; o[2] = b3x;
        o[3] = b1y; o[4] = b2y; o[5] = b3y;
        o[6] = b1z; o[7] = b2z; o[8] = b3z;
    }
    for (int idx = tid; idx < TM * 13; idx += NTHREADS) {
        int r = idx / 13, c = idx - 13 * r;
        if (c < 10)
            out_beta[(size_t)(row0 + r) * 10 + c] = Ts[r * TPAD + 144 + c];
        else
            out_cam[(size_t)(row0 + r) * 3 + (c - 10)] = Ts[r * TPAD + 154 + (c - 10)];
    }
}

// ---------------- launch ----------------
extern "C" void kernel_launch(void* const* d_in, const int* in_sizes, int n_in,
                              void* d_out, int out_size) {
    const float* x    = (const float*)d_in[0];
    // d_in[1] = pred_class (unused by reference)
    const float* W1   = (const float*)d_in[2];
    const float* b1   = (const float*)d_in[3];
    const float* W2   = (const float*)d_in[4];
    const float* b2   = (const float*)d_in[5];
    const float* W3   = (const float*)d_in[6];
    const float* b3   = (const float*)d_in[7];
    const float* icr  = (const float*)d_in[8];
    const float* ish  = (const float*)d_in[9];
    const float* icam = (const float*)d_in[10];
    float* out = (float*)d_out;

    int nrows = in_sizes[0] / 256;  // 115200

    prep_theta0_k<<<1, TPAD>>>(icr, ish, icam);
    prep_W1bp_k<<<TPAD, 256>>>(W1);
    prep_c1_k<<<1, 256>>>(W1, b1);
    prep_W23p_k<<<256, TPAD>>>(W2, W3);
    prep_b23_k<<<1, TPAD>>>(b2, b3, W3);

    int smem = (TM * TPAD + TM * 256 + TM * 16) * (int)sizeof(float);  // 55296 B
    cudaFuncSetAttribute(detr_main, cudaFuncAttributeMaxDynamicSharedMemorySize, smem);
    detr_main<<<nrows / TM, NTHREADS, smem>>>(x, W1, b1, out, nrows);
}